// round 10
// baseline (speedup 1.0000x reference)
#include <cuda_runtime.h>
#include <cuda_bf16.h>
#include <math.h>
#include <stdint.h>
#include <string.h>

#define NTOK   2048
#define DMODEL 1024
#define NHEAD  16
#define DHEAD  64
#define FEXP   4096
#define NEXP   16
#define CAP    160      // int(1.25 * 2048 / 16)
#define HGRP   4        // heads per attention group

// ---------------------------------------------------------------------------
// Scratch (single __device__ bss array; aliased). ~151 MB total.
// ---------------------------------------------------------------------------
constexpr size_t SZ_ND = (size_t)NTOK * DMODEL * 4;            // 8 MB
constexpr size_t OFF_A    = 0;               // hln planes -> ctx (fp32)
constexpr size_t OFF_B    = 1 * SZ_ND;       // qin planes -> x1 (fp32)
constexpr size_t OFF_C    = 2 * SZ_ND;       // kin planes -> h2 (fp32)
constexpr size_t OFF_D    = 3 * SZ_ND;       // vin planes
constexpr size_t OFF_E    = 4 * SZ_ND;       // q -> ye
constexpr size_t OFF_F    = 5 * SZ_ND;       // k
constexpr size_t OFF_G    = 6 * SZ_ND;       // v -> buf (spills 2.5MB into SC)
constexpr size_t OFF_SC   = 7 * SZ_ND;       // scores: HGRP x 16MB = 67MB
constexpr size_t SZ_SC    = (size_t)HGRP * NTOK * NTOK * 4;
constexpr size_t OFF_HEXP = OFF_SC + (size_t)(4 << 20);        // aliases SC tail
constexpr size_t OFF_ROUTES = OFF_SC + SZ_SC;
constexpr size_t OFF_SLOT   = OFF_ROUTES + (size_t)NTOK * 4;
constexpr size_t OFF_KEEP   = OFF_SLOT   + (size_t)NTOK * 4;
constexpr size_t OFF_PMAX   = OFF_KEEP   + (size_t)NTOK * 4;
// pre-split bf16 weight planes (live through whole attention; own region)
constexpr size_t OFF_WPL  = OFF_PMAX + (size_t)NTOK * 4;
constexpr size_t SZ_MAT   = (size_t)DMODEL * DMODEL;           // 1M elts
constexpr size_t OFF_PAKW = OFF_WPL;                           // 3 pairs: 12MB
constexpr size_t OFF_IPWP = OFF_PAKW + 3 * SZ_MAT * 4;         // 3 pairs: 12MB
constexpr size_t OFF_OPWP = OFF_IPWP + 3 * SZ_MAT * 4;         // 1 pair : 4MB
constexpr size_t OFF_PAKB = OFF_OPWP + SZ_MAT * 4;
constexpr size_t SCRATCH_BYTES = OFF_PAKB + (size_t)3 * DMODEL * 4;

__device__ __align__(256) unsigned char g_scratch[SCRATCH_BYTES];

// ---------------------------------------------------------------------------
// helpers
// ---------------------------------------------------------------------------
__device__ __forceinline__ void mma16816(float* c,
                                         uint32_t a0, uint32_t a1, uint32_t a2, uint32_t a3,
                                         uint32_t b0, uint32_t b1) {
    asm volatile(
        "mma.sync.aligned.m16n8k16.row.col.f32.bf16.bf16.f32 "
        "{%0,%1,%2,%3}, {%4,%5,%6,%7}, {%8,%9}, {%0,%1,%2,%3};"
        : "+f"(c[0]), "+f"(c[1]), "+f"(c[2]), "+f"(c[3])
        : "r"(a0), "r"(a1), "r"(a2), "r"(a3), "r"(b0), "r"(b1));
}

__device__ __forceinline__ uint32_t bf162_bits(float l0, float l1) {
    __nv_bfloat162 p = __floats2bfloat162_rn(l0, l1);
    uint32_t u;
    memcpy(&u, &p, 4);
    return u;
}

// ---------------------------------------------------------------------------
// HMMA GEMM (bf16 trunc-split-2, fp32 accumulate), mma.sync.m16n8k16.
//   C[m,n] = sum_k A[m,k]*B[n,k]  (B K-major)   TRB: B global [K,Nd] row-major
//   APRE/BPRE: operand given as pre-split bf16 planes (hi at ptr, lo at +xLo).
//   CSPLIT: write C as bf16 hi/lo planes. MINB: CTAs/SM for launch_bounds.
// ---------------------------------------------------------------------------
template<int BM, int BN, bool TRB, bool APRE, bool BPRE, bool CSPLIT,
         bool BIAS, bool RELU, bool RESID, bool MASKSCALE, bool CTRIM, int MINB>
__global__ void __launch_bounds__(256, MINB) mma_gemm(
    const void* __restrict__ Araw, const void* __restrict__ Braw,
    const float* __restrict__ bias, const float* __restrict__ resid,
    void* __restrict__ Craw,
    int M, int Nd, int K, int lda, int ldb, int ldc,
    long long sA, long long sB, long long sC, long long sBias,
    long long aLo, long long bLo, long long cLo)
{
    constexpr int BK = 32;
    constexpr int STR = 80;
    constexpr int WMW = (BM >= 128) ? 2 : 1;
    constexpr int MT  = BM / (WMW * 16);
    constexpr int WNW = 8 / WMW;
    constexpr int WNSZ = BN / WNW;
    constexpr int NT  = WNSZ / 8;
    constexpr int NA4 = BM / 32;
    constexpr int NB4 = BN / 32;
    constexpr int NAP = BM / 64;            // uint4-per-plane per thread (PRE)
    constexpr int NBP = (BN >= 64) ? BN / 64 : 1;
    constexpr int BUFB = (2 * BM + 2 * BN) * STR;

    extern __shared__ unsigned char dsm[];

    const int tid = threadIdx.x;
    const int wid = tid >> 5, lane = tid & 31;
    const int wm = (WMW == 2) ? (wid & 1) : 0;
    const int wn = (WMW == 2) ? (wid >> 1) : wid;
    const int gid = lane >> 2, tig = lane & 3;

    const unsigned short* Ap = nullptr; const float* Af = nullptr;
    const unsigned short* Bp = nullptr; const float* Bf = nullptr;
    unsigned short* Cp = nullptr; float* Cf = nullptr;
    if (APRE) Ap = (const unsigned short*)Araw + (long long)blockIdx.z * sA;
    else      Af = (const float*)Araw + (long long)blockIdx.z * sA;
    if (BPRE) Bp = (const unsigned short*)Braw + (long long)blockIdx.z * sB;
    else      Bf = (const float*)Braw + (long long)blockIdx.z * sB;
    if (CSPLIT) Cp = (unsigned short*)Craw + (long long)blockIdx.z * sC;
    else        Cf = (float*)Craw + (long long)blockIdx.z * sC;
    const float* bptr = nullptr;
    if (BIAS) bptr = bias + (long long)blockIdx.z * sBias;

    const int m0 = blockIdx.y * BM;
    const int n0 = blockIdx.x * BN;

    if (MASKSCALE) {
        int hardLim = (m0 + BM + 255) & ~255;
        if (n0 >= hardLim) return;
        if (n0 > m0 + BM - 1) {
            for (int i = tid; i < BM * BN / 4; i += 256) {
                int r = i / (BN / 4), c = (i % (BN / 4)) * 4;
                if (m0 + r < M)
                    *(float4*)&Cf[(long long)(m0 + r) * ldc + n0 + c] =
                        make_float4(-INFINITY, -INFINITY, -INFINITY, -INFINITY);
            }
            return;
        }
    }

    float acc[MT][NT][4];
    #pragma unroll
    for (int i = 0; i < MT; i++)
        #pragma unroll
        for (int j = 0; j < NT; j++)
            #pragma unroll
            for (int l = 0; l < 4; l++) acc[i][j][l] = 0.f;

    float4 aS[APRE ? 1 : NA4], bS[BPRE ? 1 : NB4];
    uint4 aH[APRE ? NAP : 1], aL[APRE ? NAP : 1];
    uint4 bH[BPRE ? NBP : 1], bL[BPRE ? NBP : 1];

    auto ldA = [&](int k0) {
        if (APRE) {
            #pragma unroll
            for (int i = 0; i < NAP; i++) {
                int j = tid + i * 256;
                int r = j >> 2, q = j & 3;
                const unsigned short* g = Ap + (long long)(m0 + r) * lda + k0 + q * 8;
                aH[i] = *(const uint4*)g;
                aL[i] = *(const uint4*)(g + aLo);
            }
        } else {
            #pragma unroll
            for (int i = 0; i < NA4; i++) {
                int j = tid + i * 256;
                int r = j >> 3, c = (j & 7) * 4;
                aS[i] = (m0 + r < M) ? *(const float4*)&Af[(long long)(m0 + r) * lda + k0 + c]
                                     : make_float4(0.f, 0.f, 0.f, 0.f);
            }
        }
    };
    auto ldB = [&](int k0) {
        if (BPRE) {
            #pragma unroll
            for (int i = 0; i < NBP; i++) {
                int j = tid + i * 256;
                int r = j >> 2, q = j & 3;
                if (BN < 64 && r >= BN) continue;
                const unsigned short* g = Bp + (long long)(n0 + r) * ldb + k0 + q * 8;
                bH[i] = *(const uint4*)g;
                bL[i] = *(const uint4*)(g + bLo);
            }
        } else if (!TRB) {
            #pragma unroll
            for (int i = 0; i < NB4; i++) {
                int j = tid + i * 256;
                int r = j >> 3, c = (j & 7) * 4;
                bS[i] = (n0 + r < Nd) ? *(const float4*)&Bf[(long long)(n0 + r) * ldb + k0 + c]
                                      : make_float4(0.f, 0.f, 0.f, 0.f);
            }
        } else {
            #pragma unroll
            for (int i = 0; i < NB4; i++) {
                int j = tid + i * 256;
                int r = j / (BN / 4), c = (j % (BN / 4)) * 4;
                bS[i] = *(const float4*)&Bf[(long long)(k0 + r) * ldb + n0 + c];
            }
        }
    };
    auto stA = [&](unsigned char* bufb) {
        unsigned char* Ah = bufb;
        unsigned char* Al = bufb + BM * STR;
        if (APRE) {
            #pragma unroll
            for (int i = 0; i < NAP; i++) {
                int j = tid + i * 256;
                int r = j >> 2, q = j & 3;
                uint32_t off = (uint32_t)(r * STR + q * 16);
                *(uint4*)(Ah + off) = aH[i];
                *(uint4*)(Al + off) = aL[i];
            }
        } else {
            #pragma unroll
            for (int i = 0; i < NA4; i++) {
                int j = tid + i * 256;
                int r = j >> 3, c4 = j & 7;
                uint4 u;
                memcpy(&u, &aS[i], 16);
                uint32_t h01 = __byte_perm(u.x, u.y, 0x7632);
                uint32_t h23 = __byte_perm(u.z, u.w, 0x7632);
                float l0 = aS[i].x - __uint_as_float(u.x & 0xffff0000u);
                float l1 = aS[i].y - __uint_as_float(u.y & 0xffff0000u);
                float l2 = aS[i].z - __uint_as_float(u.z & 0xffff0000u);
                float l3 = aS[i].w - __uint_as_float(u.w & 0xffff0000u);
                uint32_t off = (uint32_t)(r * STR + c4 * 8);
                *(uint2*)(Ah + off) = make_uint2(h01, h23);
                *(uint2*)(Al + off) = make_uint2(bf162_bits(l0, l1), bf162_bits(l2, l3));
            }
        }
    };
    auto stB = [&](unsigned char* bufb) {
        unsigned char* Bh = bufb + 2 * BM * STR;
        unsigned char* Bl = bufb + 2 * BM * STR + BN * STR;
        if (BPRE) {
            #pragma unroll
            for (int i = 0; i < NBP; i++) {
                int j = tid + i * 256;
                int r = j >> 2, q = j & 3;
                if (BN < 64 && r >= BN) continue;
                uint32_t off = (uint32_t)(r * STR + q * 16);
                *(uint4*)(Bh + off) = bH[i];
                *(uint4*)(Bl + off) = bL[i];
            }
        } else if (!TRB) {
            #pragma unroll
            for (int i = 0; i < NB4; i++) {
                int j = tid + i * 256;
                int r = j >> 3, c4 = j & 7;
                uint4 u;
                memcpy(&u, &bS[i], 16);
                uint32_t h01 = __byte_perm(u.x, u.y, 0x7632);
                uint32_t h23 = __byte_perm(u.z, u.w, 0x7632);
                float l0 = bS[i].x - __uint_as_float(u.x & 0xffff0000u);
                float l1 = bS[i].y - __uint_as_float(u.y & 0xffff0000u);
                float l2 = bS[i].z - __uint_as_float(u.z & 0xffff0000u);
                float l3 = bS[i].w - __uint_as_float(u.w & 0xffff0000u);
                uint32_t off = (uint32_t)(r * STR + c4 * 8);
                *(uint2*)(Bh + off) = make_uint2(h01, h23);
                *(uint2*)(Bl + off) = make_uint2(bf162_bits(l0, l1), bf162_bits(l2, l3));
            }
        } else {
            #pragma unroll
            for (int i = 0; i < NB4; i++) {
                int j = tid + i * 256;
                int r = j / (BN / 4), c4 = j % (BN / 4);
                float v[4] = {bS[i].x, bS[i].y, bS[i].z, bS[i].w};
                #pragma unroll
                for (int q = 0; q < 4; q++) {
                    int n = c4 * 4 + q;
                    uint32_t ub = __float_as_uint(v[q]);
                    unsigned short h = (unsigned short)(ub >> 16);
                    float lof = v[q] - __uint_as_float(ub & 0xffff0000u);
                    unsigned short l = __bfloat16_as_ushort(__float2bfloat16_rn(lof));
                    uint32_t off = (uint32_t)(n * STR + r * 2);
                    *(unsigned short*)(Bh + off) = h;
                    *(unsigned short*)(Bl + off) = l;
                }
            }
        }
    };

    auto compute = [&](unsigned char* bufb) {
        unsigned char* Ah = bufb;
        unsigned char* Al = bufb + BM * STR;
        unsigned char* Bh = bufb + 2 * BM * STR;
        unsigned char* Bl = bufb + 2 * BM * STR + BN * STR;
        #pragma unroll
        for (int ks = 0; ks < 2; ks++) {
            uint32_t a[MT][4], b[NT][2], bl[NT][2];
            const int kb = ks * 32 + tig * 4;
            #pragma unroll
            for (int ms = 0; ms < MT; ms++) {
                uint32_t ao = (uint32_t)((wm * (MT * 16) + ms * 16 + gid) * STR + kb);
                a[ms][0] = *(const uint32_t*)(Ah + ao);
                a[ms][1] = *(const uint32_t*)(Ah + ao + 8 * STR);
                a[ms][2] = *(const uint32_t*)(Ah + ao + 16);
                a[ms][3] = *(const uint32_t*)(Ah + ao + 8 * STR + 16);
            }
            #pragma unroll
            for (int ns = 0; ns < NT; ns++) {
                uint32_t bo = (uint32_t)((wn * WNSZ + ns * 8 + gid) * STR + kb);
                b[ns][0] = *(const uint32_t*)(Bh + bo);
                b[ns][1] = *(const uint32_t*)(Bh + bo + 16);
                bl[ns][0] = *(const uint32_t*)(Bl + bo);
                bl[ns][1] = *(const uint32_t*)(Bl + bo + 16);
            }
            #pragma unroll
            for (int ms = 0; ms < MT; ms++)
                #pragma unroll
                for (int ns = 0; ns < NT; ns++)
                    mma16816(acc[ms][ns], a[ms][0], a[ms][1], a[ms][2], a[ms][3],
                             b[ns][0], b[ns][1]);
            #pragma unroll
            for (int ms = 0; ms < MT; ms++)
                #pragma unroll
                for (int ns = 0; ns < NT; ns++)
                    mma16816(acc[ms][ns], a[ms][0], a[ms][1], a[ms][2], a[ms][3],
                             bl[ns][0], bl[ns][1]);
            #pragma unroll
            for (int ms = 0; ms < MT; ms++) {
                uint32_t ao = (uint32_t)((wm * (MT * 16) + ms * 16 + gid) * STR + kb);
                a[ms][0] = *(const uint32_t*)(Al + ao);
                a[ms][1] = *(const uint32_t*)(Al + ao + 8 * STR);
                a[ms][2] = *(const uint32_t*)(Al + ao + 16);
                a[ms][3] = *(const uint32_t*)(Al + ao + 8 * STR + 16);
            }
            #pragma unroll
            for (int ms = 0; ms < MT; ms++)
                #pragma unroll
                for (int ns = 0; ns < NT; ns++)
                    mma16816(acc[ms][ns], a[ms][0], a[ms][1], a[ms][2], a[ms][3],
                             b[ns][0], b[ns][1]);
        }
    };

    int nch = K >> 5;
    if (CTRIM) { int lim = (m0 + BM) >> 5; nch = nch < lim ? nch : lim; }

    ldA(0); ldB(0);
    stA(dsm); stB(dsm);
    __syncthreads();
    for (int c = 0; c < nch; c++) {
        if (c + 1 < nch) { ldA((c + 1) << 5); ldB((c + 1) << 5); }
        compute(dsm + (c & 1) * BUFB);
        if (c + 1 < nch) {
            unsigned char* nb = dsm + ((c + 1) & 1) * BUFB;
            stA(nb); stB(nb);
        }
        __syncthreads();
    }

    // ---- epilogue
    #pragma unroll
    for (int ms = 0; ms < MT; ms++) {
        #pragma unroll
        for (int ns = 0; ns < NT; ns++) {
            int m = m0 + wm * (MT * 16) + ms * 16 + gid;
            int n = n0 + wn * WNSZ + ns * 8 + tig * 2;
            float* cp = acc[ms][ns];
            #pragma unroll
            for (int half = 0; half < 2; half++) {
                int mm = m + half * 8;
                if (mm >= M) continue;
                float v0 = cp[half * 2 + 0], v1 = cp[half * 2 + 1];
                if (BIAS) { v0 += bptr[n]; v1 += bptr[n + 1]; }
                if (MASKSCALE) {
                    v0 *= 0.125f; v1 *= 0.125f;
                    if (n > mm) v0 = -INFINITY;
                    if (n + 1 > mm) v1 = -INFINITY;
                }
                if (RELU) { v0 = fmaxf(v0, 0.f); v1 = fmaxf(v1, 0.f); }
                if (RESID) {
                    float2 rr = *(const float2*)&resid[(long long)mm * ldc + n];
                    v0 += rr.x; v1 += rr.y;
                }
                if (CSPLIT) {
                    uint32_t u0 = __float_as_uint(v0), u1 = __float_as_uint(v1);
                    uint32_t hw = (u0 >> 16) | (u1 & 0xffff0000u);
                    float l0 = v0 - __uint_as_float(u0 & 0xffff0000u);
                    float l1 = v1 - __uint_as_float(u1 & 0xffff0000u);
                    uint32_t lw = bf162_bits(l0, l1);
                    *(uint32_t*)(Cp + (long long)mm * ldc + n) = hw;
                    *(uint32_t*)(Cp + cLo + (long long)mm * ldc + n) = lw;
                } else {
                    *(float2*)&Cf[(long long)mm * ldc + n] = make_float2(v0, v1);
                }
            }
        }
    }
}

// ---------------------------------------------------------------------------
// packall: pre-split all dense weights into bf16 hi/lo planes + pack biases.
// ---------------------------------------------------------------------------
__global__ void __launch_bounds__(256) packall_k(
    const float* __restrict__ wk, const float* __restrict__ wq, const float* __restrict__ wv,
    const float* __restrict__ ipw, const float* __restrict__ opw,
    const float* __restrict__ bk, const float* __restrict__ bq, const float* __restrict__ bv,
    unsigned short* __restrict__ pakw, unsigned short* __restrict__ ipwp,
    unsigned short* __restrict__ opwp, float* __restrict__ pakb)
{
    const long long MAT = (long long)DMODEL * DMODEL;   // 2^20
    long long t = (long long)blockIdx.x * 256 + threadIdx.x;
    long long e = t * 4;
    if (e < 7 * MAT) {
        int seg = (int)(e >> 20);
        long long loc = e & (MAT - 1);
        const float* src;
        unsigned short* dst;
        if (seg < 3) { src = (seg == 0) ? wk : (seg == 1) ? wq : wv; dst = pakw + seg * 2 * MAT; }
        else if (seg < 6) { int z = seg - 3; src = ipw + z * MAT; dst = ipwp + z * 2 * MAT; }
        else { src = opw; dst = opwp; }
        float4 v = *(const float4*)(src + loc);
        uint4 u;
        memcpy(&u, &v, 16);
        uint32_t h01 = __byte_perm(u.x, u.y, 0x7632);
        uint32_t h23 = __byte_perm(u.z, u.w, 0x7632);
        float l0 = v.x - __uint_as_float(u.x & 0xffff0000u);
        float l1 = v.y - __uint_as_float(u.y & 0xffff0000u);
        float l2 = v.z - __uint_as_float(u.z & 0xffff0000u);
        float l3 = v.w - __uint_as_float(u.w & 0xffff0000u);
        *(uint2*)(dst + loc)       = make_uint2(h01, h23);
        *(uint2*)(dst + MAT + loc) = make_uint2(bf162_bits(l0, l1), bf162_bits(l2, l3));
    }
    if (t < 3 * DMODEL / 4) {
        constexpr int B4 = DMODEL / 4;
        const float* src = (t < B4) ? bk : (t < 2 * B4) ? bq : bv;
        long long loc = t - (t < B4 ? 0 : (t < 2 * B4 ? B4 : 2 * B4));
        ((float4*)pakb)[t] = ((const float4*)src)[loc];
    }
}

// ---------------------------------------------------------------------------
// Block reductions + glue kernels
// ---------------------------------------------------------------------------
__device__ __forceinline__ float blockReduceSum(float val, float* red) {
    int lane = threadIdx.x & 31, wid = threadIdx.x >> 5;
    #pragma unroll
    for (int o = 16; o; o >>= 1) val += __shfl_down_sync(0xffffffffu, val, o);
    __syncthreads();
    if (lane == 0) red[wid] = val;
    __syncthreads();
    if (threadIdx.x < 32) {
        val = (lane < 8) ? red[lane] : 0.f;
        #pragma unroll
        for (int o = 4; o; o >>= 1) val += __shfl_down_sync(0xffffffffu, val, o);
        if (lane == 0) red[0] = val;
    }
    __syncthreads();
    return red[0];
}
__device__ __forceinline__ float blockReduceMax(float val, float* red) {
    int lane = threadIdx.x & 31, wid = threadIdx.x >> 5;
    #pragma unroll
    for (int o = 16; o; o >>= 1) val = fmaxf(val, __shfl_down_sync(0xffffffffu, val, o));
    __syncthreads();
    if (lane == 0) red[wid] = val;
    __syncthreads();
    if (threadIdx.x < 32) {
        val = (lane < 8) ? red[lane] : -INFINITY;
        #pragma unroll
        for (int o = 4; o; o >>= 1) val = fmaxf(val, __shfl_down_sync(0xffffffffu, val, o));
        if (lane == 0) red[0] = val;
    }
    __syncthreads();
    return red[0];
}

// LayerNorm. SPLIT: emit bf16 hi/lo planes
template<bool SPLIT>
__global__ void __launch_bounds__(256) ln_k(const float* __restrict__ x,
                                            const float* __restrict__ w,
                                            const float* __restrict__ b,
                                            void* __restrict__ out) {
    __shared__ float red[8];
    int row = blockIdx.x, tid = threadIdx.x;
    const float* xr = x + (size_t)row * DMODEL;
    float v[4];
    float s = 0.f;
    #pragma unroll
    for (int i = 0; i < 4; i++) { v[i] = xr[tid + i * 256]; s += v[i]; }
    s = blockReduceSum(s, red);
    float mu = s * (1.f / DMODEL);
    float s2 = 0.f;
    #pragma unroll
    for (int i = 0; i < 4; i++) { float d = v[i] - mu; s2 += d * d; }
    s2 = blockReduceSum(s2, red);
    float rstd = rsqrtf(s2 * (1.f / DMODEL) + 1e-5f);
    #pragma unroll
    for (int i = 0; i < 4; i++) {
        int c = tid + i * 256;
        float o = (v[i] - mu) * rstd * w[c] + b[c];
        if (SPLIT) {
            unsigned short* oh = (unsigned short*)out;
            uint32_t u = __float_as_uint(o);
            oh[(size_t)row * DMODEL + c] = (unsigned short)(u >> 16);
            float lo = o - __uint_as_float(u & 0xffff0000u);
            oh[(size_t)NTOK * DMODEL + (size_t)row * DMODEL + c] =
                __bfloat16_as_ushort(__float2bfloat16_rn(lo));
        } else {
            ((float*)out)[(size_t)row * DMODEL + c] = o;
        }
    }
}

// Triangular softmax
__global__ void __launch_bounds__(256) softmax_k(float* __restrict__ S) {
    __shared__ float red[8];
    int r = blockIdx.x & (NTOK - 1);
    float* row = S + (long long)blockIdx.x * NTOK;
    int tid = threadIdx.x;
    int nit = (r >> 8) + 1;
    float v[8];
    float mx = -INFINITY;
    #pragma unroll
    for (int i = 0; i < 8; i++) {
        if (i < nit) { v[i] = row[tid + i * 256]; mx = fmaxf(mx, v[i]); }
    }
    mx = blockReduceMax(mx, red);
    float s = 0.f;
    #pragma unroll
    for (int i = 0; i < 8; i++) {
        if (i < nit) { v[i] = expf(v[i] - mx); s += v[i]; }
    }
    s = blockReduceSum(s, red);
    float inv = 1.f / s;
    #pragma unroll
    for (int i = 0; i < 8; i++) {
        if (i < nit) row[tid + i * 256] = v[i] * inv;
    }
}

__global__ void __launch_bounds__(512) router_k(const float* __restrict__ h,
                                                const float* __restrict__ rw,
                                                const float* __restrict__ rb,
                                                int* __restrict__ routes,
                                                float* __restrict__ pmax) {
    __shared__ float lg[NEXP];
    int t = blockIdx.x;
    int wid = threadIdx.x >> 5, lane = threadIdx.x & 31;
    const float* hr = h + (size_t)t * DMODEL;
    const float* wr = rw + (size_t)wid * DMODEL;
    float s = 0.f;
    for (int k = lane; k < DMODEL; k += 32) s += hr[k] * wr[k];
    #pragma unroll
    for (int o = 16; o; o >>= 1) s += __shfl_down_sync(0xffffffffu, s, o);
    if (lane == 0) lg[wid] = s + rb[wid];
    __syncthreads();
    if (threadIdx.x == 0) {
        float mx = lg[0]; int arg = 0;
        #pragma unroll
        for (int e = 1; e < NEXP; e++)
            if (lg[e] > mx) { mx = lg[e]; arg = e; }
        float sum = 0.f;
        #pragma unroll
        for (int e = 0; e < NEXP; e++) sum += expf(lg[e] - mx);
        routes[t] = arg;
        pmax[t] = 1.f / sum;
    }
}

__global__ void __launch_bounds__(512) slot_k(const int* __restrict__ routes,
                                              int* __restrict__ slot,
                                              int* __restrict__ keep) {
    __shared__ int sr[NTOK];
    int tid = threadIdx.x;
    for (int i = tid; i < NTOK; i += 512) sr[i] = routes[i];
    __syncthreads();
    int wid = tid >> 5, lane = tid & 31;
    int pos = 0;
    unsigned lmask = (1u << lane) - 1u;
    for (int base = 0; base < NTOK; base += 32) {
        int r = sr[base + lane];
        unsigned m = __ballot_sync(0xffffffffu, r == wid);
        if (r == wid) {
            int p = pos + __popc(m & lmask);
            int kp = (p < CAP) ? 1 : 0;
            keep[base + lane] = kp;
            slot[base + lane] = kp ? (wid * CAP + p) : (NEXP * CAP);
        }
        pos += __popc(m);
    }
}

__global__ void __launch_bounds__(256) gather_k(const float* __restrict__ h,
                                                const int* __restrict__ slot,
                                                const int* __restrict__ keep,
                                                float* __restrict__ buf) {
    int t = blockIdx.x;
    if (!keep[t]) return;
    int s = slot[t];
    const float4* src = (const float4*)(h + (size_t)t * DMODEL);
    float4* dst = (float4*)(buf + (size_t)s * DMODEL);
    dst[threadIdx.x] = src[threadIdx.x];
}

__global__ void __launch_bounds__(256) final_k(const float* __restrict__ x1,
                                               const float* __restrict__ h2,
                                               const float* __restrict__ ye,
                                               const int* __restrict__ slot,
                                               const int* __restrict__ keep,
                                               const float* __restrict__ pmax,
                                               float* __restrict__ out) {
    int t = blockIdx.x;
    float p = pmax[t];
    const float4* ysrc = keep[t]
        ? (const float4*)(ye + (size_t)slot[t] * DMODEL)
        : (const float4*)(h2 + (size_t)t * DMODEL);
    const float4* xs = (const float4*)(x1 + (size_t)t * DMODEL);
    float4 a = xs[threadIdx.x];
    float4 y = ysrc[threadIdx.x];
    float4 o = make_float4(a.x + y.x * p, a.y + y.y * p, a.z + y.z * p, a.w + y.w * p);
    ((float4*)out)[(size_t)t * (DMODEL / 4) + threadIdx.x] = o;
}

// ---------------------------------------------------------------------------
// Launch
// ---------------------------------------------------------------------------
extern "C" void kernel_launch(void* const* d_in, const int* in_sizes, int n_in,
                              void* d_out, int out_size) {
    const float* x    = (const float*)d_in[0];
    const float* wk   = (const float*)d_in[1];
    const float* bk   = (const float*)d_in[2];
    const float* wq   = (const float*)d_in[3];
    const float* bq   = (const float*)d_in[4];
    const float* wv   = (const float*)d_in[5];
    const float* bv   = (const float*)d_in[6];
    const float* ipw  = (const float*)d_in[7];
    const float* ipb  = (const float*)d_in[8];
    const float* opw  = (const float*)d_in[9];
    const float* opb  = (const float*)d_in[10];
    const float* ln1w = (const float*)d_in[11];
    const float* ln1b = (const float*)d_in[12];
    const float* ln2w = (const float*)d_in[13];
    const float* ln2b = (const float*)d_in[14];
    const float* rw   = (const float*)d_in[15];
    const float* rb   = (const float*)d_in[16];
    const float* w1   = (const float*)d_in[17];
    const float* b1   = (const float*)d_in[18];
    const float* w2   = (const float*)d_in[19];
    const float* b2   = (const float*)d_in[20];
    float* out = (float*)d_out;

    void* sp = nullptr;
    cudaGetSymbolAddress(&sp, g_scratch);
    char* base = (char*)sp;
    unsigned short* hlnP = (unsigned short*)(base + OFF_A);
    float* ctx    = (float*)(base + OFF_A);
    unsigned short* qinP = (unsigned short*)(base + OFF_B);
    float* x1     = (float*)(base + OFF_B);
    float* h2     = (float*)(base + OFF_C);
    float* q      = (float*)(base + OFF_E);
    float* ye     = (float*)(base + OFF_E);
    float* k      = (float*)(base + OFF_F);
    float* v      = (float*)(base + OFF_G);
    float* buf    = (float*)(base + OFF_G);
    float* sc     = (float*)(base + OFF_SC);
    float* hexp   = (float*)(base + OFF_HEXP);
    unsigned short* pakw = (unsigned short*)(base + OFF_PAKW);
    unsigned short* ipwp = (unsigned short*)(base + OFF_IPWP);
    unsigned short* opwp = (unsigned short*)(base + OFF_OPWP);
    float* pakb   = (float*)(base + OFF_PAKB);
    int*   routes = (int*)(base + OFF_ROUTES);
    int*   slot   = (int*)(base + OFF_SLOT);
    int*   keep   = (int*)(base + OFF_KEEP);
    float* pmax   = (float*)(base + OFF_PMAX);

    constexpr long long MAT = (long long)DMODEL * DMODEL;     // 1M
    constexpr long long NDE = (long long)NTOK * DMODEL;       // 2M

    // instantiations: plane GEMMs at BN=64 / 2 CTAs-per-SM; rest round-8 shapes
    auto GPS  = mma_gemm<128, 64,  false, true,  true,  true,  true,  false, false, false, false, 2>;
    auto GIP  = mma_gemm<128, 64,  false, true,  true,  false, true,  false, false, false, false, 2>;
    auto GPR  = mma_gemm<128, 128, false, false, true,  false, true,  false, true,  false, false, 1>;
    auto GQK  = mma_gemm<128, 128, false, false, false, false, false, false, false, true,  false, 1>;
    auto GPV  = mma_gemm<64,  64,  true,  false, false, false, false, false, false, false, true,  1>;
    auto GW1  = mma_gemm<160, 128, false, false, false, false, true,  true,  false, false, false, 1>;
    auto GW2  = mma_gemm<160, 128, false, false, false, false, true,  false, false, false, false, 1>;
    constexpr int SMP  = 2 * (2 * 128 + 2 * 64)  * 80;    // 61440 (plane, BN=64)
    constexpr int SM128 = 2 * (2 * 128 + 2 * 128) * 80;   // 81920
    constexpr int SM64  = 2 * (2 * 64  + 2 * 64)  * 80;   // 40960
    constexpr int SM160 = 2 * (2 * 160 + 2 * 128) * 80;   // 92160
    cudaFuncSetAttribute(GPS, cudaFuncAttributeMaxDynamicSharedMemorySize, SMP);
    cudaFuncSetAttribute(GIP, cudaFuncAttributeMaxDynamicSharedMemorySize, SMP);
    cudaFuncSetAttribute(GPR, cudaFuncAttributeMaxDynamicSharedMemorySize, SM128);
    cudaFuncSetAttribute(GQK, cudaFuncAttributeMaxDynamicSharedMemorySize, SM128);
    cudaFuncSetAttribute(GPV, cudaFuncAttributeMaxDynamicSharedMemorySize, SM64);
    cudaFuncSetAttribute(GW1, cudaFuncAttributeMaxDynamicSharedMemorySize, SM160);
    cudaFuncSetAttribute(GW2, cudaFuncAttributeMaxDynamicSharedMemorySize, SM160);

    // ---- LN1 (emits hln planes) + weight pre-split (independent)
    ln_k<true><<<NTOK, 256>>>(x, ln1w, ln1b, hlnP);
    packall_k<<<(int)((7 * MAT / 4 + 255) / 256), 256>>>(
        wk, wq, wv, ipw, opw, bk, bq, bv, pakw, ipwp, opwp, pakb);

    // ---- first projections: one z=3 launch, planes in -> planes out (2 CTA/SM)
    dim3 gD3(DMODEL / 64, NTOK / 128, 3);
    GPS<<<gD3, 256, SMP>>>(hlnP, pakw, pakb, nullptr, qinP,
        NTOK, DMODEL, DMODEL, DMODEL, DMODEL, DMODEL,
        0, 2 * MAT, 2 * NDE, DMODEL, NDE, MAT, NDE);

    // ---- in_proj: planes in -> q/k/v fp32 (2 CTA/SM)
    GIP<<<gD3, 256, SMP>>>(qinP, ipwp, ipb, nullptr, q,
        NTOK, DMODEL, DMODEL, DMODEL, DMODEL, DMODEL,
        2 * NDE, 2 * MAT, NDE, DMODEL, NDE, MAT, 0);

    // ---- attention: groups of HGRP heads, z-batched
    for (int g = 0; g < NHEAD / HGRP; g++) {
        const int ho = g * HGRP * DHEAD;
        dim3 gS(NTOK / 128, NTOK / 128, HGRP);
        GQK<<<gS, 256, SM128>>>(q + ho, k + ho, nullptr, nullptr, sc,
            NTOK, NTOK, DHEAD, DMODEL, DMODEL, NTOK,
            DHEAD, DHEAD, (long long)NTOK * NTOK, 0, 0, 0, 0);
        softmax_k<<<HGRP * NTOK, 256>>>(sc);
        dim3 gV(1, NTOK / 64, HGRP);
        GPV<<<gV, 256, SM64>>>(sc, v + ho, nullptr, nullptr, ctx + ho,
            NTOK, DHEAD, NTOK, NTOK, DMODEL, DMODEL,
            (long long)NTOK * NTOK, DHEAD, DHEAD, 0, 0, 0, 0);
    }

    // ---- x1 = x + ctx @ opw^T + opb  (B planes)
    dim3 gD(DMODEL / 128, NTOK / 128, 1);
    GPR<<<gD, 256, SM128>>>(ctx, opwp, opb, x, x1,
        NTOK, DMODEL, DMODEL, DMODEL, DMODEL, DMODEL,
        0, 0, 0, 0, 0, MAT, 0);

    // ---- LN2 (fp32 out)
    ln_k<false><<<NTOK, 256>>>(x1, ln2w, ln2b, h2);

    // ---- router + routing + gather
    router_k<<<NTOK, 512>>>(h2, rw, rb, routes, pmax);
    slot_k<<<1, 512>>>(routes, slot, keep);
    gather_k<<<NTOK, 256>>>(h2, slot, keep, buf);

    // ---- expert FFN layer 1 (relu): single BM=160 launch
    dim3 g1(FEXP / 128, 1, NEXP);
    GW1<<<g1, 256, SM160>>>(buf, w1, b1, nullptr, hexp,
        CAP, FEXP, DMODEL, DMODEL, DMODEL, FEXP,
        (long long)CAP * DMODEL, (long long)FEXP * DMODEL,
        (long long)CAP * FEXP, FEXP, 0, 0, 0);

    // ---- expert FFN layer 2: single BM=160 launch
    dim3 g2(DMODEL / 128, 1, NEXP);
    GW2<<<g2, 256, SM160>>>(hexp, w2, b2, nullptr, ye,
        CAP, DMODEL, FEXP, FEXP, FEXP, DMODEL,
        (long long)CAP * FEXP, (long long)DMODEL * FEXP,
        (long long)CAP * DMODEL, DMODEL, 0, 0, 0);

    // ---- final combine
    final_k<<<NTOK, 256>>>(x1, h2, ye, slot, keep, pmax, out);
}

// round 11
// speedup vs baseline: 1.1081x; 1.1081x over previous
#include <cuda_runtime.h>
#include <cuda_bf16.h>
#include <math.h>
#include <stdint.h>
#include <string.h>

#define NTOK   2048
#define DMODEL 1024
#define NHEAD  16
#define DHEAD  64
#define FEXP   4096
#define NEXP   16
#define CAP    160      // int(1.25 * 2048 / 16)
#define HGRP   4        // heads per attention group

// ---------------------------------------------------------------------------
// Scratch (single __device__ bss array; aliased). ~123 MB total.
// ---------------------------------------------------------------------------
constexpr size_t SZ_ND = (size_t)NTOK * DMODEL * 4;            // 8 MB
constexpr size_t OFF_A    = 0;               // hln -> ctx
constexpr size_t OFF_B    = 1 * SZ_ND;       // qin -> x1
constexpr size_t OFF_C    = 2 * SZ_ND;       // kin -> h2
constexpr size_t OFF_D    = 3 * SZ_ND;       // vin
constexpr size_t OFF_E    = 4 * SZ_ND;       // q -> ye
constexpr size_t OFF_F    = 5 * SZ_ND;       // k
constexpr size_t OFF_G    = 6 * SZ_ND;       // v -> buf (spills 2.5MB into SC)
constexpr size_t OFF_SC   = 7 * SZ_ND;       // scores: HGRP x 16MB = 67MB
constexpr size_t SZ_SC    = (size_t)HGRP * NTOK * NTOK * 4;
constexpr size_t OFF_HEXP = OFF_SC + (size_t)(4 << 20);        // clear of buf spill
constexpr size_t OFF_PAKW = OFF_HEXP;                          // 12 MB (pack region)
constexpr size_t OFF_PAKB = OFF_PAKW + (size_t)3 * DMODEL * DMODEL * 4;
constexpr size_t OFF_ROUTES = OFF_SC + SZ_SC;
constexpr size_t OFF_SLOT   = OFF_ROUTES + (size_t)NTOK * 4;
constexpr size_t OFF_KEEP   = OFF_SLOT   + (size_t)NTOK * 4;
constexpr size_t OFF_PMAX   = OFF_KEEP   + (size_t)NTOK * 4;
constexpr size_t SCRATCH_BYTES = OFF_PMAX + (size_t)NTOK * 4;

__device__ __align__(256) unsigned char g_scratch[SCRATCH_BYTES];

// ---------------------------------------------------------------------------
// helpers
// ---------------------------------------------------------------------------
__device__ __forceinline__ void mma16816(float* c,
                                         uint32_t a0, uint32_t a1, uint32_t a2, uint32_t a3,
                                         uint32_t b0, uint32_t b1) {
    asm volatile(
        "mma.sync.aligned.m16n8k16.row.col.f32.bf16.bf16.f32 "
        "{%0,%1,%2,%3}, {%4,%5,%6,%7}, {%8,%9}, {%0,%1,%2,%3};"
        : "+f"(c[0]), "+f"(c[1]), "+f"(c[2]), "+f"(c[3])
        : "r"(a0), "r"(a1), "r"(a2), "r"(a3), "r"(b0), "r"(b1));
}

__device__ __forceinline__ void ldsm_x4(uint32_t* r, uint32_t saddr) {
    asm volatile("ldmatrix.sync.aligned.m8n8.x4.shared.b16 {%0,%1,%2,%3}, [%4];"
        : "=r"(r[0]), "=r"(r[1]), "=r"(r[2]), "=r"(r[3]) : "r"(saddr));
}
__device__ __forceinline__ void ldsm_x2(uint32_t* r, uint32_t saddr) {
    asm volatile("ldmatrix.sync.aligned.m8n8.x2.shared.b16 {%0,%1}, [%2];"
        : "=r"(r[0]), "=r"(r[1]) : "r"(saddr));
}

__device__ __forceinline__ uint32_t bf162_bits(float l0, float l1) {
    __nv_bfloat162 p = __floats2bfloat162_rn(l0, l1);
    uint32_t u;
    memcpy(&u, &p, 4);
    return u;
}

// ---------------------------------------------------------------------------
// HMMA GEMM (bf16 trunc-split-2, fp32 accumulate), mma.sync + ldmatrix.
//   C[m,n] = sum_k A[m,k]*B[n,k]  (B K-major)   TRB: B global [K,Nd] row-major
//   BM in {160,128,64}; BK=32; BN in {64,128}. 256 thr = 8 warps, 1 CTA/SM.
// ---------------------------------------------------------------------------
template<int BM, int BN, bool TRB, bool BIAS, bool RELU, bool RESID, bool MASKSCALE, bool CTRIM>
__global__ void __launch_bounds__(256, 1) mma_gemm(
    const float* __restrict__ A, const float* __restrict__ B,
    const float* __restrict__ bias, const float* __restrict__ resid,
    float* __restrict__ C,
    int M, int Nd, int K, int lda, int ldb, int ldc,
    long long sA, long long sB, long long sC, long long sBias)
{
    constexpr int BK = 32;
    constexpr int STR = 80;                 // bytes per smem row (32 bf16 + pad)
    constexpr int WMW = (BM >= 128) ? 2 : 1;
    constexpr int MT  = BM / (WMW * 16);
    constexpr int WNW = 8 / WMW;
    constexpr int WNSZ = BN / WNW;
    constexpr int NT  = WNSZ / 8;
    constexpr int NA4 = BM / 32;
    constexpr int NB4 = BN / 32;
    constexpr int BUFB = (2 * BM + 2 * BN) * STR;

    extern __shared__ unsigned char dsm[];

    const int tid = threadIdx.x;
    const int wid = tid >> 5, lane = tid & 31;
    const int wm = (WMW == 2) ? (wid & 1) : 0;
    const int wn = (WMW == 2) ? (wid >> 1) : wid;
    const int gid = lane >> 2, tig = lane & 3;
    const uint32_t dsm_s = (uint32_t)__cvta_generic_to_shared(dsm);
    const uint32_t laneA = (uint32_t)((lane & 15) * STR + (lane >> 4) * 16);
    const uint32_t laneB = (uint32_t)((lane & 7) * STR + ((lane >> 3) & 1) * 16);

    A += (long long)blockIdx.z * sA;
    B += (long long)blockIdx.z * sB;
    C += (long long)blockIdx.z * sC;
    const float* bptr = nullptr;
    if (BIAS) bptr = bias + (long long)blockIdx.z * sBias;

    const int m0 = blockIdx.y * BM;
    const int n0 = blockIdx.x * BN;

    if (MASKSCALE) {
        int hardLim = (m0 + BM + 255) & ~255;   // beyond triangular-softmax reads
        if (n0 >= hardLim) return;
        if (n0 > m0 + BM - 1) {   // fully masked tile: fill -inf, skip compute
            for (int i = tid; i < BM * BN / 4; i += 256) {
                int r = i / (BN / 4), c = (i % (BN / 4)) * 4;
                if (m0 + r < M)
                    *(float4*)&C[(long long)(m0 + r) * ldc + n0 + c] =
                        make_float4(-INFINITY, -INFINITY, -INFINITY, -INFINITY);
            }
            return;
        }
    }

    float acc[MT][NT][4];
    #pragma unroll
    for (int i = 0; i < MT; i++)
        #pragma unroll
        for (int j = 0; j < NT; j++)
            #pragma unroll
            for (int l = 0; l < 4; l++) acc[i][j][l] = 0.f;

    float4 aS[NA4], bS[NB4];

    auto ldA = [&](int k0) {
        #pragma unroll
        for (int i = 0; i < NA4; i++) {
            int j = tid + i * 256;
            int r = j >> 3, c = (j & 7) * 4;
            aS[i] = (m0 + r < M) ? *(const float4*)&A[(long long)(m0 + r) * lda + k0 + c]
                                 : make_float4(0.f, 0.f, 0.f, 0.f);
        }
    };
    auto ldB = [&](int k0) {
        if (!TRB) {
            #pragma unroll
            for (int i = 0; i < NB4; i++) {
                int j = tid + i * 256;
                int r = j >> 3, c = (j & 7) * 4;
                bS[i] = (n0 + r < Nd) ? *(const float4*)&B[(long long)(n0 + r) * ldb + k0 + c]
                                      : make_float4(0.f, 0.f, 0.f, 0.f);
            }
        } else {
            #pragma unroll
            for (int i = 0; i < NB4; i++) {
                int j = tid + i * 256;
                int r = j / (BN / 4), c = (j % (BN / 4)) * 4;
                bS[i] = *(const float4*)&B[(long long)(k0 + r) * ldb + n0 + c];
            }
        }
    };
    auto stA = [&](unsigned char* bufb) {
        unsigned char* Ah = bufb;
        unsigned char* Al = bufb + BM * STR;
        #pragma unroll
        for (int i = 0; i < NA4; i++) {
            int j = tid + i * 256;
            int r = j >> 3, c4 = j & 7;
            uint4 u;
            memcpy(&u, &aS[i], 16);
            uint32_t h01 = __byte_perm(u.x, u.y, 0x7632);
            uint32_t h23 = __byte_perm(u.z, u.w, 0x7632);
            float l0 = aS[i].x - __uint_as_float(u.x & 0xffff0000u);
            float l1 = aS[i].y - __uint_as_float(u.y & 0xffff0000u);
            float l2 = aS[i].z - __uint_as_float(u.z & 0xffff0000u);
            float l3 = aS[i].w - __uint_as_float(u.w & 0xffff0000u);
            uint32_t off = (uint32_t)(r * STR + c4 * 8);
            *(uint2*)(Ah + off) = make_uint2(h01, h23);
            *(uint2*)(Al + off) = make_uint2(bf162_bits(l0, l1), bf162_bits(l2, l3));
        }
    };
    auto stB = [&](unsigned char* bufb) {
        unsigned char* Bh = bufb + 2 * BM * STR;
        unsigned char* Bl = bufb + 2 * BM * STR + BN * STR;
        if (!TRB) {
            #pragma unroll
            for (int i = 0; i < NB4; i++) {
                int j = tid + i * 256;
                int r = j >> 3, c4 = j & 7;
                uint4 u;
                memcpy(&u, &bS[i], 16);
                uint32_t h01 = __byte_perm(u.x, u.y, 0x7632);
                uint32_t h23 = __byte_perm(u.z, u.w, 0x7632);
                float l0 = bS[i].x - __uint_as_float(u.x & 0xffff0000u);
                float l1 = bS[i].y - __uint_as_float(u.y & 0xffff0000u);
                float l2 = bS[i].z - __uint_as_float(u.z & 0xffff0000u);
                float l3 = bS[i].w - __uint_as_float(u.w & 0xffff0000u);
                uint32_t off = (uint32_t)(r * STR + c4 * 8);
                *(uint2*)(Bh + off) = make_uint2(h01, h23);
                *(uint2*)(Bl + off) = make_uint2(bf162_bits(l0, l1), bf162_bits(l2, l3));
            }
        } else {
            #pragma unroll
            for (int i = 0; i < NB4; i++) {
                int j = tid + i * 256;
                int r = j / (BN / 4), c4 = j % (BN / 4);
                float v[4] = {bS[i].x, bS[i].y, bS[i].z, bS[i].w};
                #pragma unroll
                for (int q = 0; q < 4; q++) {
                    int n = c4 * 4 + q;
                    uint32_t ub = __float_as_uint(v[q]);
                    unsigned short h = (unsigned short)(ub >> 16);
                    float lof = v[q] - __uint_as_float(ub & 0xffff0000u);
                    unsigned short l = __bfloat16_as_ushort(__float2bfloat16_rn(lof));
                    uint32_t off = (uint32_t)(n * STR + r * 2);
                    *(unsigned short*)(Bh + off) = h;
                    *(unsigned short*)(Bl + off) = l;
                }
            }
        }
    };

    auto compute = [&](uint32_t bufo) {
        const uint32_t AhS = dsm_s + bufo;
        const uint32_t AlS = AhS + BM * STR;
        const uint32_t BhS = dsm_s + bufo + 2 * BM * STR;
        const uint32_t BlS = BhS + BN * STR;
        #pragma unroll
        for (int ks = 0; ks < 2; ks++) {
            const uint32_t kb = (uint32_t)(ks * 32);
            uint32_t a[MT][4], b[NT][2], bl[NT][2];
            #pragma unroll
            for (int ms = 0; ms < MT; ms++)
                ldsm_x4(a[ms], AhS + (uint32_t)((wm * (MT * 16) + ms * 16) * STR) + kb + laneA);
            #pragma unroll
            for (int ns = 0; ns < NT; ns++) {
                uint32_t bo = (uint32_t)((wn * WNSZ + ns * 8) * STR) + kb + laneB;
                ldsm_x2(b[ns],  BhS + bo);
                ldsm_x2(bl[ns], BlS + bo);
            }
            #pragma unroll
            for (int ms = 0; ms < MT; ms++)
                #pragma unroll
                for (int ns = 0; ns < NT; ns++)
                    mma16816(acc[ms][ns], a[ms][0], a[ms][1], a[ms][2], a[ms][3],
                             b[ns][0], b[ns][1]);
            #pragma unroll
            for (int ms = 0; ms < MT; ms++)
                #pragma unroll
                for (int ns = 0; ns < NT; ns++)
                    mma16816(acc[ms][ns], a[ms][0], a[ms][1], a[ms][2], a[ms][3],
                             bl[ns][0], bl[ns][1]);
            #pragma unroll
            for (int ms = 0; ms < MT; ms++)
                ldsm_x4(a[ms], AlS + (uint32_t)((wm * (MT * 16) + ms * 16) * STR) + kb + laneA);
            #pragma unroll
            for (int ms = 0; ms < MT; ms++)
                #pragma unroll
                for (int ns = 0; ns < NT; ns++)
                    mma16816(acc[ms][ns], a[ms][0], a[ms][1], a[ms][2], a[ms][3],
                             b[ns][0], b[ns][1]);
        }
    };

    int nch = K >> 5;
    if (CTRIM) { int lim = (m0 + BM) >> 5; nch = nch < lim ? nch : lim; }

    ldA(0); ldB(0);
    stA(dsm); stB(dsm);
    __syncthreads();
    for (int c = 0; c < nch; c++) {
        if (c + 1 < nch) { ldA((c + 1) << 5); ldB((c + 1) << 5); }
        compute((uint32_t)((c & 1) * BUFB));
        if (c + 1 < nch) {
            unsigned char* nb = dsm + ((c + 1) & 1) * BUFB;
            stA(nb); stB(nb);
        }
        __syncthreads();
    }

    // ---- epilogue: direct stores from accumulators
    #pragma unroll
    for (int ms = 0; ms < MT; ms++) {
        #pragma unroll
        for (int ns = 0; ns < NT; ns++) {
            int m = m0 + wm * (MT * 16) + ms * 16 + gid;
            int n = n0 + wn * WNSZ + ns * 8 + tig * 2;
            float* cp = acc[ms][ns];
            #pragma unroll
            for (int half = 0; half < 2; half++) {
                int mm = m + half * 8;
                if (mm >= M) continue;
                float v0 = cp[half * 2 + 0], v1 = cp[half * 2 + 1];
                if (BIAS) { v0 += bptr[n]; v1 += bptr[n + 1]; }
                if (MASKSCALE) {
                    v0 *= 0.125f; v1 *= 0.125f;
                    if (n > mm) v0 = -INFINITY;
                    if (n + 1 > mm) v1 = -INFINITY;
                }
                if (RELU) { v0 = fmaxf(v0, 0.f); v1 = fmaxf(v1, 0.f); }
                if (RESID) {
                    float2 rr = *(const float2*)&resid[(long long)mm * ldc + n];
                    v0 += rr.x; v1 += rr.y;
                }
                *(float2*)&C[(long long)mm * ldc + n] = make_float2(v0, v1);
            }
        }
    }
}

// ---------------------------------------------------------------------------
// Pack wk|wq|wv and bk|bq|bv into contiguous scratch for one z=3 launch
// ---------------------------------------------------------------------------
__global__ void __launch_bounds__(256) pack3_k(
    const float* __restrict__ a0, const float* __restrict__ a1, const float* __restrict__ a2,
    const float* __restrict__ b0, const float* __restrict__ b1, const float* __restrict__ b2,
    float* __restrict__ w, float* __restrict__ b)
{
    constexpr int N4 = DMODEL * DMODEL / 4;
    int idx = blockIdx.x * 256 + threadIdx.x;
    if (idx < 3 * N4) {
        const float* src = (idx < N4) ? a0 : (idx < 2 * N4) ? a1 : a2;
        int loc = idx - (idx < N4 ? 0 : (idx < 2 * N4 ? N4 : 2 * N4));
        ((float4*)w)[idx] = ((const float4*)src)[loc];
    }
    if (idx < 3 * DMODEL / 4) {
        constexpr int B4 = DMODEL / 4;
        const float* src = (idx < B4) ? b0 : (idx < 2 * B4) ? b1 : b2;
        int loc = idx - (idx < B4 ? 0 : (idx < 2 * B4 ? B4 : 2 * B4));
        ((float4*)b)[idx] = ((const float4*)src)[loc];
    }
}

// ---------------------------------------------------------------------------
// Block reductions + glue kernels
// ---------------------------------------------------------------------------
__device__ __forceinline__ float blockReduceSum(float val, float* red) {
    int lane = threadIdx.x & 31, wid = threadIdx.x >> 5;
    #pragma unroll
    for (int o = 16; o; o >>= 1) val += __shfl_down_sync(0xffffffffu, val, o);
    __syncthreads();
    if (lane == 0) red[wid] = val;
    __syncthreads();
    if (threadIdx.x < 32) {
        val = (lane < 8) ? red[lane] : 0.f;
        #pragma unroll
        for (int o = 4; o; o >>= 1) val += __shfl_down_sync(0xffffffffu, val, o);
        if (lane == 0) red[0] = val;
    }
    __syncthreads();
    return red[0];
}
__device__ __forceinline__ float blockReduceMax(float val, float* red) {
    int lane = threadIdx.x & 31, wid = threadIdx.x >> 5;
    #pragma unroll
    for (int o = 16; o; o >>= 1) val = fmaxf(val, __shfl_down_sync(0xffffffffu, val, o));
    __syncthreads();
    if (lane == 0) red[wid] = val;
    __syncthreads();
    if (threadIdx.x < 32) {
        val = (lane < 8) ? red[lane] : -INFINITY;
        #pragma unroll
        for (int o = 4; o; o >>= 1) val = fmaxf(val, __shfl_down_sync(0xffffffffu, val, o));
        if (lane == 0) red[0] = val;
    }
    __syncthreads();
    return red[0];
}

__global__ void __launch_bounds__(256) ln_k(const float* __restrict__ x,
                                            const float* __restrict__ w,
                                            const float* __restrict__ b,
                                            float* __restrict__ out) {
    __shared__ float red[8];
    int row = blockIdx.x, tid = threadIdx.x;
    const float* xr = x + (size_t)row * DMODEL;
    float v[4];
    float s = 0.f;
    #pragma unroll
    for (int i = 0; i < 4; i++) { v[i] = xr[tid + i * 256]; s += v[i]; }
    s = blockReduceSum(s, red);
    float mu = s * (1.f / DMODEL);
    float s2 = 0.f;
    #pragma unroll
    for (int i = 0; i < 4; i++) { float d = v[i] - mu; s2 += d * d; }
    s2 = blockReduceSum(s2, red);
    float rstd = rsqrtf(s2 * (1.f / DMODEL) + 1e-5f);
    float* orow = out + (size_t)row * DMODEL;
    #pragma unroll
    for (int i = 0; i < 4; i++) {
        int c = tid + i * 256;
        orow[c] = (v[i] - mu) * rstd * w[c] + b[c];
    }
}

// Triangular softmax: row r only processes ceil((r+1)/256)*256 columns.
__global__ void __launch_bounds__(256) softmax_k(float* __restrict__ S) {
    __shared__ float red[8];
    int r = blockIdx.x & (NTOK - 1);
    float* row = S + (long long)blockIdx.x * NTOK;
    int tid = threadIdx.x;
    int nit = (r >> 8) + 1;
    float v[8];
    float mx = -INFINITY;
    #pragma unroll
    for (int i = 0; i < 8; i++) {
        if (i < nit) { v[i] = row[tid + i * 256]; mx = fmaxf(mx, v[i]); }
    }
    mx = blockReduceMax(mx, red);
    float s = 0.f;
    #pragma unroll
    for (int i = 0; i < 8; i++) {
        if (i < nit) { v[i] = expf(v[i] - mx); s += v[i]; }
    }
    s = blockReduceSum(s, red);
    float inv = 1.f / s;
    #pragma unroll
    for (int i = 0; i < 8; i++) {
        if (i < nit) row[tid + i * 256] = v[i] * inv;
    }
}

__global__ void __launch_bounds__(512) router_k(const float* __restrict__ h,
                                                const float* __restrict__ rw,
                                                const float* __restrict__ rb,
                                                int* __restrict__ routes,
                                                float* __restrict__ pmax) {
    __shared__ float lg[NEXP];
    int t = blockIdx.x;
    int wid = threadIdx.x >> 5, lane = threadIdx.x & 31;
    const float* hr = h + (size_t)t * DMODEL;
    const float* wr = rw + (size_t)wid * DMODEL;
    float s = 0.f;
    for (int k = lane; k < DMODEL; k += 32) s += hr[k] * wr[k];
    #pragma unroll
    for (int o = 16; o; o >>= 1) s += __shfl_down_sync(0xffffffffu, s, o);
    if (lane == 0) lg[wid] = s + rb[wid];
    __syncthreads();
    if (threadIdx.x == 0) {
        float mx = lg[0]; int arg = 0;
        #pragma unroll
        for (int e = 1; e < NEXP; e++)
            if (lg[e] > mx) { mx = lg[e]; arg = e; }
        float sum = 0.f;
        #pragma unroll
        for (int e = 0; e < NEXP; e++) sum += expf(lg[e] - mx);
        routes[t] = arg;
        pmax[t] = 1.f / sum;
    }
}

__global__ void __launch_bounds__(512) slot_k(const int* __restrict__ routes,
                                              int* __restrict__ slot,
                                              int* __restrict__ keep) {
    __shared__ int sr[NTOK];
    int tid = threadIdx.x;
    for (int i = tid; i < NTOK; i += 512) sr[i] = routes[i];
    __syncthreads();
    int wid = tid >> 5, lane = tid & 31;
    int pos = 0;
    unsigned lmask = (1u << lane) - 1u;
    for (int base = 0; base < NTOK; base += 32) {
        int r = sr[base + lane];
        unsigned m = __ballot_sync(0xffffffffu, r == wid);
        if (r == wid) {
            int p = pos + __popc(m & lmask);
            int kp = (p < CAP) ? 1 : 0;
            keep[base + lane] = kp;
            slot[base + lane] = kp ? (wid * CAP + p) : (NEXP * CAP);
        }
        pos += __popc(m);
    }
}

__global__ void __launch_bounds__(256) gather_k(const float* __restrict__ h,
                                                const int* __restrict__ slot,
                                                const int* __restrict__ keep,
                                                float* __restrict__ buf) {
    int t = blockIdx.x;
    if (!keep[t]) return;
    int s = slot[t];
    const float4* src = (const float4*)(h + (size_t)t * DMODEL);
    float4* dst = (float4*)(buf + (size_t)s * DMODEL);
    dst[threadIdx.x] = src[threadIdx.x];
}

__global__ void __launch_bounds__(256) final_k(const float* __restrict__ x1,
                                               const float* __restrict__ h2,
                                               const float* __restrict__ ye,
                                               const int* __restrict__ slot,
                                               const int* __restrict__ keep,
                                               const float* __restrict__ pmax,
                                               float* __restrict__ out) {
    int t = blockIdx.x;
    float p = pmax[t];
    const float4* ysrc = keep[t]
        ? (const float4*)(ye + (size_t)slot[t] * DMODEL)
        : (const float4*)(h2 + (size_t)t * DMODEL);
    const float4* xs = (const float4*)(x1 + (size_t)t * DMODEL);
    float4 a = xs[threadIdx.x];
    float4 y = ysrc[threadIdx.x];
    float4 o = make_float4(a.x + y.x * p, a.y + y.y * p, a.z + y.z * p, a.w + y.w * p);
    ((float4*)out)[(size_t)t * (DMODEL / 4) + threadIdx.x] = o;
}

// ---------------------------------------------------------------------------
// Launch
// ---------------------------------------------------------------------------
extern "C" void kernel_launch(void* const* d_in, const int* in_sizes, int n_in,
                              void* d_out, int out_size) {
    const float* x    = (const float*)d_in[0];
    const float* wk   = (const float*)d_in[1];
    const float* bk   = (const float*)d_in[2];
    const float* wq   = (const float*)d_in[3];
    const float* bq   = (const float*)d_in[4];
    const float* wv   = (const float*)d_in[5];
    const float* bv   = (const float*)d_in[6];
    const float* ipw  = (const float*)d_in[7];
    const float* ipb  = (const float*)d_in[8];
    const float* opw  = (const float*)d_in[9];
    const float* opb  = (const float*)d_in[10];
    const float* ln1w = (const float*)d_in[11];
    const float* ln1b = (const float*)d_in[12];
    const float* ln2w = (const float*)d_in[13];
    const float* ln2b = (const float*)d_in[14];
    const float* rw   = (const float*)d_in[15];
    const float* rb   = (const float*)d_in[16];
    const float* w1   = (const float*)d_in[17];
    const float* b1   = (const float*)d_in[18];
    const float* w2   = (const float*)d_in[19];
    const float* b2   = (const float*)d_in[20];
    float* out = (float*)d_out;

    void* sp = nullptr;
    cudaGetSymbolAddress(&sp, g_scratch);
    char* base = (char*)sp;
    float* hln    = (float*)(base + OFF_A);
    float* ctx    = (float*)(base + OFF_A);
    float* qin    = (float*)(base + OFF_B);
    float* x1     = (float*)(base + OFF_B);
    float* kin    = (float*)(base + OFF_C);
    float* h2     = (float*)(base + OFF_C);
    float* vin    = (float*)(base + OFF_D);
    float* q      = (float*)(base + OFF_E);
    float* ye     = (float*)(base + OFF_E);
    float* k      = (float*)(base + OFF_F);
    float* v      = (float*)(base + OFF_G);
    float* buf    = (float*)(base + OFF_G);
    float* sc     = (float*)(base + OFF_SC);
    float* hexp   = (float*)(base + OFF_HEXP);
    float* pakw   = (float*)(base + OFF_PAKW);
    float* pakb   = (float*)(base + OFF_PAKB);
    int*   routes = (int*)(base + OFF_ROUTES);
    int*   slot   = (int*)(base + OFF_SLOT);
    int*   keep   = (int*)(base + OFF_KEEP);
    float* pmax   = (float*)(base + OFF_PMAX);
    (void)kin; (void)vin; (void)hln;

    // instantiations + dynamic smem opt-in (round-8 configs, LDSM inside)
    auto GP   = mma_gemm<128, 128, false, true,  false, false, false, false>;  // proj
    auto GPR  = mma_gemm<128, 128, false, true,  false, true,  false, false>;  // out-proj+resid
    auto GQK  = mma_gemm<128, 128, false, false, false, false, true,  false>;  // QK^T masked
    auto GPV  = mma_gemm<64,  64,  true,  false, false, false, false, true >;  // P@V causal-trim
    auto GW1  = mma_gemm<160, 128, false, true,  true,  false, false, false>;  // w1+relu
    auto GW2  = mma_gemm<160, 128, false, true,  false, false, false, false>;  // w2
    constexpr int SM128 = 2 * (2 * 128 + 2 * 128) * 80;   // 81920
    constexpr int SM64  = 2 * (2 * 64  + 2 * 64)  * 80;   // 40960
    constexpr int SM160 = 2 * (2 * 160 + 2 * 128) * 80;   // 92160
    cudaFuncSetAttribute(GP,  cudaFuncAttributeMaxDynamicSharedMemorySize, SM128);
    cudaFuncSetAttribute(GPR, cudaFuncAttributeMaxDynamicSharedMemorySize, SM128);
    cudaFuncSetAttribute(GQK, cudaFuncAttributeMaxDynamicSharedMemorySize, SM128);
    cudaFuncSetAttribute(GPV, cudaFuncAttributeMaxDynamicSharedMemorySize, SM64);
    cudaFuncSetAttribute(GW1, cudaFuncAttributeMaxDynamicSharedMemorySize, SM160);
    cudaFuncSetAttribute(GW2, cudaFuncAttributeMaxDynamicSharedMemorySize, SM160);

    // ---- LN1 + weight packing (independent)
    ln_k<<<NTOK, 256>>>(x, ln1w, ln1b, hln);
    pack3_k<<<(3 * DMODEL * DMODEL / 4 + 255) / 256, 256>>>(
        wk, wq, wv, bk, bq, bv, pakw, pakb);

    // ---- first projections: ONE z=3 batched launch
    //      (swapped K/Q per reference: z order wk,wq,wv -> qin,kin,vin)
    dim3 gD3(DMODEL / 128, NTOK / 128, 3);
    GP<<<gD3, 256, SM128>>>(hln, pakw, pakb, nullptr, qin,
        NTOK, DMODEL, DMODEL, DMODEL, DMODEL, DMODEL,
        0, (long long)DMODEL * DMODEL, (long long)NTOK * DMODEL, DMODEL);

    // ---- in_proj splits: one batched launch
    GP<<<gD3, 256, SM128>>>(qin, ipw, ipb, nullptr, q,
        NTOK, DMODEL, DMODEL, DMODEL, DMODEL, DMODEL,
        (long long)NTOK * DMODEL, (long long)DMODEL * DMODEL,
        (long long)NTOK * DMODEL, DMODEL);

    // ---- attention: groups of HGRP heads, z-batched
    for (int g = 0; g < NHEAD / HGRP; g++) {
        const int ho = g * HGRP * DHEAD;
        dim3 gS(NTOK / 128, NTOK / 128, HGRP);
        GQK<<<gS, 256, SM128>>>(q + ho, k + ho, nullptr, nullptr, sc,
            NTOK, NTOK, DHEAD, DMODEL, DMODEL, NTOK,
            DHEAD, DHEAD, (long long)NTOK * NTOK, 0);
        softmax_k<<<HGRP * NTOK, 256>>>(sc);
        dim3 gV(1, NTOK / 64, HGRP);
        GPV<<<gV, 256, SM64>>>(sc, v + ho, nullptr, nullptr, ctx + ho,
            NTOK, DHEAD, NTOK, NTOK, DMODEL, DMODEL,
            (long long)NTOK * NTOK, DHEAD, DHEAD, 0);
    }

    // ---- x1 = x + ctx @ opw^T + opb
    dim3 gD(DMODEL / 128, NTOK / 128, 1);
    GPR<<<gD, 256, SM128>>>(ctx, opw, opb, x, x1,
        NTOK, DMODEL, DMODEL, DMODEL, DMODEL, DMODEL, 0, 0, 0, 0);

    // ---- LN2
    ln_k<<<NTOK, 256>>>(x1, ln2w, ln2b, h2);

    // ---- router + routing + gather
    router_k<<<NTOK, 512>>>(h2, rw, rb, routes, pmax);
    slot_k<<<1, 512>>>(routes, slot, keep);
    gather_k<<<NTOK, 256>>>(h2, slot, keep, buf);

    // ---- expert FFN layer 1 (relu): single BM=160 launch
    dim3 g1(FEXP / 128, 1, NEXP);
    GW1<<<g1, 256, SM160>>>(buf, w1, b1, nullptr, hexp,
        CAP, FEXP, DMODEL, DMODEL, DMODEL, FEXP,
        (long long)CAP * DMODEL, (long long)FEXP * DMODEL,
        (long long)CAP * FEXP, FEXP);

    // ---- expert FFN layer 2: single BM=160 launch
    dim3 g2(DMODEL / 128, 1, NEXP);
    GW2<<<g2, 256, SM160>>>(hexp, w2, b2, nullptr, ye,
        CAP, DMODEL, FEXP, FEXP, FEXP, DMODEL,
        (long long)CAP * FEXP, (long long)DMODEL * FEXP,
        (long long)CAP * DMODEL, DMODEL);

    // ---- final combine
    final_k<<<NTOK, 256>>>(x1, h2, ye, slot, keep, pmax, out);
}